// round 11
// baseline (speedup 1.0000x reference)
#include <cuda_runtime.h>
#include <math_constants.h>

// KNN min-dist, 9x9 window, C=3, zero-padded.
// d^2 = |t|^2 + (|o|^2 - 2 t.o). Packed f32x2 across dj-pairs with PACK-FREE
// streaming operands: SoA planes stored twice (copyB shifted one column) so
// (dj,dj+1) pairs load as one aligned ld.shared.b64. dj=8 handled scalar.
// MLP-batched tile-fill prologue. Fixed shapes: B=4, C=3, H=256, W=512.

#define BDIM 128
#define TW 32
#define TH 16
#define TY 4
#define HALO 4
#define SW 9

#define B_ 4
#define H_ 256
#define W_ 512
#define HW_ (H_*W_)

#define SH_H (TH + 2*HALO)   // 24
#define NCOL 41              // tile cols 0..40 (40 used + 1 spare)
#define PSTR 88              // o-plane row stride: copyA @0..40, copyB @44..83
#define BOFF 44              // copyB word offset (even -> b64 stays 8B aligned)
#define QSTR 44              // q-plane row stride (single copy)
#define NR (TY + SW - 1)     // 12
#define NELEM (SH_H * NCOL)  // 984

typedef unsigned long long u64;

__device__ __forceinline__ u64 pk2(float lo, float hi){
    u64 r; asm("mov.b64 %0, {%1,%2};" : "=l"(r) : "f"(lo), "f"(hi)); return r;
}
__device__ __forceinline__ void upk2(u64 v, float& lo, float& hi){
    asm("mov.b64 {%0,%1}, %2;" : "=f"(lo), "=f"(hi) : "l"(v));
}
__device__ __forceinline__ u64 fma2(u64 a, u64 b, u64 c){
    u64 r; asm("fma.rn.f32x2 %0, %1, %2, %3;" : "=l"(r) : "l"(a), "l"(b), "l"(c)); return r;
}

__global__ __launch_bounds__(BDIM, 7) void knn_min_kernel(
    const float* __restrict__ tfm, const float* __restrict__ obs,
    float* __restrict__ out)
{
    __shared__ __align__(16) float p0s[SH_H * PSTR];
    __shared__ __align__(16) float p1s[SH_H * PSTR];
    __shared__ __align__(16) float p2s[SH_H * PSTR];
    __shared__ __align__(16) float qs [SH_H * QSTR];

    const int b  = blockIdx.z;
    const int x0 = blockIdx.x * TW;
    const int y0 = blockIdx.y * TH;
    const int tid = threadIdx.x;
    const int tx = tid & 31;
    const int ty = tid >> 5;

    const float* obs_b = obs + b * 3 * HW_;
    const float* tfm_b = tfm + b * 3 * HW_;

    // ---- prologue phase 1: batch-issue all obs loads (MLP), zero-padded ----
    float v0[8], v1[8], v2[8];
#pragma unroll
    for (int l = 0; l < 8; l++) {
        int idx = tid + l * BDIM;
        int iy = idx / NCOL;
        int ix = idx - iy * NCOL;
        int gy = y0 - HALO + iy;
        int gx = x0 - HALO + ix;
        bool ok = (idx < NELEM) & (gy >= 0) & (gy < H_) & (gx >= 0) & (gx < W_);
        int g = gy * W_ + gx;
        v0[l] = ok ? obs_b[g] : 0.f;
        v1[l] = ok ? obs_b[HW_ + g] : 0.f;
        v2[l] = ok ? obs_b[2 * HW_ + g] : 0.f;
    }
    // tfm loads hoisted here too (independent of smem)
    const int ybase = y0 + ty * TY;
    const int xg = x0 + tx;
    float ta[TY], tc[TY], te[TY];
#pragma unroll
    for (int k = 0; k < TY; k++) {
        int g = (ybase + k) * W_ + xg;
        ta[k] = tfm_b[g];
        tc[k] = tfm_b[HW_ + g];
        te[k] = tfm_b[2 * HW_ + g];
    }
    // ---- prologue phase 2: dual-copy stores + q ----
#pragma unroll
    for (int l = 0; l < 8; l++) {
        int idx = tid + l * BDIM;
        if (idx < NELEM) {
            int iy = idx / NCOL;
            int ix = idx - iy * NCOL;
            float a = v0[l], c = v1[l], e = v2[l];
            p0s[iy * PSTR + ix] = a;
            p1s[iy * PSTR + ix] = c;
            p2s[iy * PSTR + ix] = e;
            if (ix >= 1) {
                p0s[iy * PSTR + BOFF + ix - 1] = a;
                p1s[iy * PSTR + BOFF + ix - 1] = c;
                p2s[iy * PSTR + BOFF + ix - 1] = e;
            }
            if (ix < QSTR)
                qs[iy * QSTR + ix] = fmaf(e, e, fmaf(c, c, a * a));
        }
    }
    __syncthreads();

    // ---- per-pixel constants ----
    u64 NT0[TY], NT1[TY], NT2[TY];
    float n0f[TY], n1f[TY], n2f[TY], tt[TY], m0[TY], m1[TY];
#pragma unroll
    for (int k = 0; k < TY; k++) {
        n0f[k] = -2.f * ta[k];
        n1f[k] = -2.f * tc[k];
        n2f[k] = -2.f * te[k];
        NT0[k] = pk2(n0f[k], n0f[k]);
        NT1[k] = pk2(n1f[k], n1f[k]);
        NT2[k] = pk2(n2f[k], n2f[k]);
        tt[k]  = fmaf(te[k], te[k], fmaf(tc[k], tc[k], ta[k] * ta[k]));
        m0[k] = CUDART_INF_F;
        m1[k] = CUDART_INF_F;
    }

    // even lanes read copyA at word tx; odd lanes copyB at word tx-1
    const int sel2 = (tx & 1) ? (BOFF + tx - 1) : tx;
    const int rb = ty * TY;

    // ---- packed dj-pairs (0,1)(2,3)(4,5)(6,7) ----
#pragma unroll 1
    for (int j = 0; j < 4; j++) {
        const float* b0 = p0s + rb * PSTR + sel2 + 2 * j;
        const float* b1 = p1s + rb * PSTR + sel2 + 2 * j;
        const float* b2 = p2s + rb * PSTR + sel2 + 2 * j;
        const float* bq = qs  + rb * QSTR + tx   + 2 * j;
#pragma unroll
        for (int r = 0; r < NR; r++) {
            u64 P0 = *(const u64*)(b0 + r * PSTR);
            u64 P1 = *(const u64*)(b1 + r * PSTR);
            u64 P2 = *(const u64*)(b2 + r * PSTR);
            u64 QQ = pk2(bq[r * QSTR], bq[r * QSTR + 1]);
#pragma unroll
            for (int k = 0; k < TY; k++) {
                if (r >= k && r <= k + 8) {
                    u64 E = fma2(NT0[k], P0,
                            fma2(NT1[k], P1,
                            fma2(NT2[k], P2, QQ)));
                    float elo, ehi;
                    upk2(E, elo, ehi);
                    m0[k] = fminf(m0[k], elo);
                    m1[k] = fminf(m1[k], ehi);
                }
            }
        }
    }

    // ---- scalar pass dj=8 ----
    {
        const float* a0 = p0s + rb * PSTR + tx + 8;
        const float* a1 = p1s + rb * PSTR + tx + 8;
        const float* a2 = p2s + rb * PSTR + tx + 8;
        const float* aq = qs  + rb * QSTR + tx + 8;
#pragma unroll
        for (int r = 0; r < NR; r++) {
            float w0 = a0[r * PSTR];
            float w1 = a1[r * PSTR];
            float w2 = a2[r * PSTR];
            float wq = aq[r * QSTR];
#pragma unroll
            for (int k = 0; k < TY; k++) {
                if (r >= k && r <= k + 8) {
                    float e = fmaf(n0f[k], w0,
                              fmaf(n1f[k], w1,
                              fmaf(n2f[k], w2, wq)));
                    m0[k] = fminf(m0[k], e);
                }
            }
        }
    }

    float* out_b = out + b * HW_;
#pragma unroll
    for (int k = 0; k < TY; k++) {
        float m = fminf(m0[k], m1[k]);
        out_b[(ybase + k) * W_ + xg] = sqrtf(fmaxf(tt[k] + m, 0.f));
    }
}

extern "C" void kernel_launch(void* const* d_in, const int* in_sizes, int n_in,
                              void* d_out, int out_size)
{
    const float* tfm = (const float*)d_in[0];
    const float* obs = (const float*)d_in[1];
    float* out = (float*)d_out;
    (void)in_sizes; (void)n_in; (void)out_size;

    dim3 grid(W_ / TW, H_ / TH, B_);   // 16 x 16 x 4 = 1024 blocks
    dim3 block(BDIM);
    knn_min_kernel<<<grid, block>>>(tfm, obs, out);
}